// round 4
// baseline (speedup 1.0000x reference)
#include <cuda_runtime.h>
#include <math_constants.h>

#define NROWS 4096
#define M_REC 4000
#define M_SUB 20000
#define MAXG  10

// Scratch (allocation-free per harness rules)
__device__ int   g_ri[NROWS];
__device__ int   g_si[NROWS];
__device__ float g_pself[NROWS];

// ---------------------------------------------------------------------------
// Row argmax: one block per row, float4 vectorized, 4-way unrolled for MLP.
// Tie-break: first (smallest) index, matching jnp.argmax.
// ---------------------------------------------------------------------------
template <int M>
__global__ void __launch_bounds__(256) row_argmax_kernel(
    const float* __restrict__ mat, int* __restrict__ out_idx)
{
    const int row = blockIdx.x;
    const float4* __restrict__ rp =
        reinterpret_cast<const float4*>(mat + (size_t)row * M);
    constexpr int M4 = M / 4;   // both 4000 and 20000 divisible by 4

    float best = -CUDART_INF_F;
    int   bidx = 0;

    // Within a thread the visited indices are strictly increasing, so a
    // strict '>' keeps the first occurrence of any max automatically.
    int i = threadIdx.x;
    // 4-way unrolled main loop: 4 independent float4 loads in flight
    for (; i + 3 * 256 < M4; i += 4 * 256) {
        float4 v0 = rp[i];
        float4 v1 = rp[i + 256];
        float4 v2 = rp[i + 2 * 256];
        float4 v3 = rp[i + 3 * 256];
        #define UPD(vv, bb)                                                  \
            { int b = (bb) * 4;                                              \
              if (vv.x > best) { best = vv.x; bidx = b;     }                \
              if (vv.y > best) { best = vv.y; bidx = b + 1; }                \
              if (vv.z > best) { best = vv.z; bidx = b + 2; }                \
              if (vv.w > best) { best = vv.w; bidx = b + 3; } }
        UPD(v0, i);
        UPD(v1, i + 256);
        UPD(v2, i + 2 * 256);
        UPD(v3, i + 3 * 256);
    }
    for (; i < M4; i += 256) {
        float4 v = rp[i];
        UPD(v, i);
        #undef UPD
    }

    // Warp reduce (tie-break: smaller index wins on equal value)
    #pragma unroll
    for (int off = 16; off > 0; off >>= 1) {
        float ov = __shfl_down_sync(0xFFFFFFFFu, best, off);
        int   oi = __shfl_down_sync(0xFFFFFFFFu, bidx, off);
        if (ov > best || (ov == best && oi < bidx)) { best = ov; bidx = oi; }
    }

    // Block reduce across 8 warps
    __shared__ float s_val[8];
    __shared__ int   s_idx[8];
    const int wid = threadIdx.x >> 5;
    const int lid = threadIdx.x & 31;
    if (lid == 0) { s_val[wid] = best; s_idx[wid] = bidx; }
    __syncthreads();
    if (wid == 0) {
        best = (lid < 8) ? s_val[lid] : -CUDART_INF_F;
        bidx = (lid < 8) ? s_idx[lid] : 0x7FFFFFFF;
        #pragma unroll
        for (int off = 4; off > 0; off >>= 1) {
            float ov = __shfl_down_sync(0xFFFFFFFFu, best, off);
            int   oi = __shfl_down_sync(0xFFFFFFFFu, bidx, off);
            if (ov > best || (ov == best && oi < bidx)) { best = ov; bidx = oi; }
        }
        if (lid == 0) out_idx[row] = bidx;
    }
}

// ---------------------------------------------------------------------------
// Gathers: p_self, Tprefer (out[0:N]), Thaptic (out[2N:3N])
// NOTE: Vid is int32 on-device (JAX default config downcasts jnp.int64).
// ---------------------------------------------------------------------------
__global__ void gather_kernel(const float* __restrict__ preference,
                              const float* __restrict__ structure,
                              const int* __restrict__ Vid,
                              float* __restrict__ out)
{
    const int i = blockIdx.x * blockDim.x + threadIdx.x;
    if (i >= NROWS) return;
    const int r = g_ri[i];
    const int s = g_si[i];
    const float ps = __ldg(&preference[(size_t)s * NROWS + i]);
    g_pself[i] = ps;
    const int v = Vid[MAXG + r];                 // vid_s[ri[i]], 0 <= v < P
    const float po = __ldg(&preference[(size_t)v * NROWS + i]);
    out[i] = ps - po;                                              // Tprefer
    out[2 * NROWS + i] = __ldg(&structure[(size_t)s * M_REC + r]); // Thaptic
}

// ---------------------------------------------------------------------------
// Tsocial (out[N:2N]): all si + p_self fit in 32 KB shared; each thread owns
// one row i and scans all j (shared broadcast: all lanes read same j).
// ---------------------------------------------------------------------------
__global__ void __launch_bounds__(256) tsocial_kernel(float* __restrict__ out)
{
    __shared__ int   ss[NROWS];
    __shared__ float pp[NROWS];
    for (int j = threadIdx.x; j < NROWS; j += 256) {
        ss[j] = g_si[j];
        pp[j] = g_pself[j];
    }
    __syncthreads();

    const int i = blockIdx.x * 256 + threadIdx.x;
    const int   si_i = ss[i];
    const float p_i  = pp[i];
    float acc = 0.0f;
    #pragma unroll 8
    for (int j = 0; j < NROWS; j++) {
        if (ss[j] == si_i) acc += fminf(p_i, pp[j]);
    }
    // Loop above included j == i (si_i == si_i always); remove self term.
    acc -= p_i;   // fminf(p_i, p_i) == p_i
    out[NROWS + i] = acc;
}

// ---------------------------------------------------------------------------
extern "C" void kernel_launch(void* const* d_in, const int* in_sizes, int n_in,
                              void* d_out, int out_size)
{
    const float* Recommended_m = (const float*)d_in[0];
    const float* Substitute_m  = (const float*)d_in[1];
    // d_in[2] ItemGroups_m : unused
    const int*   Vid           = (const int*)d_in[3];
    // d_in[4..7] VUU/KUU/Vscore/Kscore : unused
    const float* preference    = (const float*)d_in[8];
    const float* structure     = (const float*)d_in[9];
    float* out = (float*)d_out;

    int* d_ri; int* d_si;
    cudaGetSymbolAddress((void**)&d_ri, g_ri);
    cudaGetSymbolAddress((void**)&d_si, g_si);

    row_argmax_kernel<M_REC><<<NROWS, 256>>>(Recommended_m, d_ri);
    row_argmax_kernel<M_SUB><<<NROWS, 256>>>(Substitute_m, d_si);
    gather_kernel<<<(NROWS + 255) / 256, 256>>>(preference, structure, Vid, out);
    tsocial_kernel<<<NROWS / 256, 256>>>(out);
}

// round 5
// speedup vs baseline: 1.3665x; 1.3665x over previous
#include <cuda_runtime.h>
#include <math_constants.h>

#define NROWS 4096
#define M_REC 4000
#define M_SUB 20000
#define MAXG  10
#define NJSL  16            // j-slices for Tsocial stage 1
#define JLEN  (NROWS/NJSL)  // 256 j per slice

// Scratch (allocation-free per harness rules)
__device__ int   g_ri[NROWS];
__device__ int   g_si[NROWS];
__device__ float g_pself[NROWS];
__device__ float g_part[NJSL * NROWS];

// ---------------------------------------------------------------------------
// Row argmax: one block per row, float4 vectorized, 4-way unrolled for MLP.
// Tie-break: first (smallest) index, matching jnp.argmax.
// ---------------------------------------------------------------------------
template <int M>
__global__ void __launch_bounds__(256) row_argmax_kernel(
    const float* __restrict__ mat, int* __restrict__ out_idx)
{
    const int row = blockIdx.x;
    const float4* __restrict__ rp =
        reinterpret_cast<const float4*>(mat + (size_t)row * M);
    constexpr int M4 = M / 4;   // both 4000 and 20000 divisible by 4

    float best = -CUDART_INF_F;
    int   bidx = 0;

    // Within a thread the visited indices are strictly increasing, so a
    // strict '>' keeps the first occurrence of any max automatically.
    int i = threadIdx.x;
    for (; i + 3 * 256 < M4; i += 4 * 256) {
        float4 v0 = rp[i];
        float4 v1 = rp[i + 256];
        float4 v2 = rp[i + 2 * 256];
        float4 v3 = rp[i + 3 * 256];
        #define UPD(vv, bb)                                                  \
            { int b = (bb) * 4;                                              \
              if (vv.x > best) { best = vv.x; bidx = b;     }                \
              if (vv.y > best) { best = vv.y; bidx = b + 1; }                \
              if (vv.z > best) { best = vv.z; bidx = b + 2; }                \
              if (vv.w > best) { best = vv.w; bidx = b + 3; } }
        UPD(v0, i);
        UPD(v1, i + 256);
        UPD(v2, i + 2 * 256);
        UPD(v3, i + 3 * 256);
    }
    for (; i < M4; i += 256) {
        float4 v = rp[i];
        UPD(v, i);
        #undef UPD
    }

    // Warp reduce (tie-break: smaller index wins on equal value)
    #pragma unroll
    for (int off = 16; off > 0; off >>= 1) {
        float ov = __shfl_down_sync(0xFFFFFFFFu, best, off);
        int   oi = __shfl_down_sync(0xFFFFFFFFu, bidx, off);
        if (ov > best || (ov == best && oi < bidx)) { best = ov; bidx = oi; }
    }

    // Block reduce across 8 warps
    __shared__ float s_val[8];
    __shared__ int   s_idx[8];
    const int wid = threadIdx.x >> 5;
    const int lid = threadIdx.x & 31;
    if (lid == 0) { s_val[wid] = best; s_idx[wid] = bidx; }
    __syncthreads();
    if (wid == 0) {
        best = (lid < 8) ? s_val[lid] : -CUDART_INF_F;
        bidx = (lid < 8) ? s_idx[lid] : 0x7FFFFFFF;
        #pragma unroll
        for (int off = 4; off > 0; off >>= 1) {
            float ov = __shfl_down_sync(0xFFFFFFFFu, best, off);
            int   oi = __shfl_down_sync(0xFFFFFFFFu, bidx, off);
            if (ov > best || (ov == best && oi < bidx)) { best = ov; bidx = oi; }
        }
        if (lid == 0) out_idx[row] = bidx;
    }
}

// ---------------------------------------------------------------------------
// Gathers: p_self, Tprefer (out[0:N]), Thaptic (out[2N:3N])
// NOTE: Vid is int32 on-device (JAX default config downcasts jnp.int64).
// ---------------------------------------------------------------------------
__global__ void gather_kernel(const float* __restrict__ preference,
                              const float* __restrict__ structure,
                              const int* __restrict__ Vid,
                              float* __restrict__ out)
{
    const int i = blockIdx.x * blockDim.x + threadIdx.x;
    if (i >= NROWS) return;
    const int r = g_ri[i];
    const int s = g_si[i];
    const float ps = __ldg(&preference[(size_t)s * NROWS + i]);
    g_pself[i] = ps;
    const int v = Vid[MAXG + r];                 // vid_s[ri[i]], 0 <= v < P
    const float po = __ldg(&preference[(size_t)v * NROWS + i]);
    out[i] = ps - po;                                              // Tprefer
    out[2 * NROWS + i] = __ldg(&structure[(size_t)s * M_REC + r]); // Thaptic
}

// ---------------------------------------------------------------------------
// Tsocial stage 1: 16 i-tiles x 16 j-slices = 256 blocks (fills the chip).
// Each thread owns one i, scans one 256-entry j-slice from shared (packed
// int2 {si, p} -> one LDS.64 per iteration). Deterministic partials.
// ---------------------------------------------------------------------------
__global__ void __launch_bounds__(256) tsocial_partial_kernel()
{
    const int itile = blockIdx.x & (NJSL - 1);
    const int jsl   = blockIdx.x >> 4;

    __shared__ int2 sj[JLEN];
    {
        const int j = jsl * JLEN + threadIdx.x;
        sj[threadIdx.x] = make_int2(g_si[j], __float_as_int(g_pself[j]));
    }
    __syncthreads();

    const int i    = itile * 256 + threadIdx.x;
    const int si_i = g_si[i];
    const float p_i = g_pself[i];
    float acc = 0.0f;
    #pragma unroll 8
    for (int jj = 0; jj < JLEN; jj++) {
        const int2 v = sj[jj];
        if (v.x == si_i) acc += fminf(p_i, __int_as_float(v.y));
    }
    g_part[jsl * NROWS + i] = acc;
}

// Tsocial stage 2: sum the 16 partials, subtract self-term, write out[N:2N].
__global__ void __launch_bounds__(256) tsocial_reduce_kernel(float* __restrict__ out)
{
    const int i = blockIdx.x * 256 + threadIdx.x;
    float acc = 0.0f;
    #pragma unroll
    for (int s = 0; s < NJSL; s++) acc += g_part[s * NROWS + i];
    // The scan included j == i (si_i == si_i always); fminf(p_i,p_i) == p_i.
    out[NROWS + i] = acc - g_pself[i];
}

// ---------------------------------------------------------------------------
extern "C" void kernel_launch(void* const* d_in, const int* in_sizes, int n_in,
                              void* d_out, int out_size)
{
    const float* Recommended_m = (const float*)d_in[0];
    const float* Substitute_m  = (const float*)d_in[1];
    // d_in[2] ItemGroups_m : unused
    const int*   Vid           = (const int*)d_in[3];
    // d_in[4..7] VUU/KUU/Vscore/Kscore : unused
    const float* preference    = (const float*)d_in[8];
    const float* structure     = (const float*)d_in[9];
    float* out = (float*)d_out;

    int* d_ri; int* d_si;
    cudaGetSymbolAddress((void**)&d_ri, g_ri);
    cudaGetSymbolAddress((void**)&d_si, g_si);

    row_argmax_kernel<M_REC><<<NROWS, 256>>>(Recommended_m, d_ri);
    row_argmax_kernel<M_SUB><<<NROWS, 256>>>(Substitute_m, d_si);
    gather_kernel<<<(NROWS + 255) / 256, 256>>>(preference, structure, Vid, out);
    tsocial_partial_kernel<<<NJSL * NJSL, 256>>>();
    tsocial_reduce_kernel<<<NROWS / 256, 256>>>(out);
}

// round 6
// speedup vs baseline: 1.4785x; 1.0819x over previous
#include <cuda_runtime.h>
#include <math_constants.h>

#define NROWS 4096
#define M_REC 4000
#define M_SUB 20000
#define MAXG  10
#define NJSL  16            // j-slices for Tsocial stage 1
#define JLEN  (NROWS/NJSL)  // 256 j per slice

// Scratch (allocation-free per harness rules)
__device__ int   g_ri[NROWS];
__device__ int   g_si[NROWS];
__device__ float g_pself[NROWS];
__device__ float g_part[NJSL * NROWS];

// ---------------------------------------------------------------------------
// Row argmax: one block per row, float4 vectorized.
// Scan carries only (best value, best VECTOR index) -> dependent chain is
// 2 ops per 16B instead of 8. Lane within the winning vector recovered
// post-scan with one reload (exact bit equality; no arithmetic on best).
// Tie-break: first (smallest) index, matching jnp.argmax.
// ---------------------------------------------------------------------------
template <int M>
__device__ __forceinline__ void row_argmax(const float* __restrict__ mat,
                                           int row, int* __restrict__ out_idx)
{
    const float4* __restrict__ rp =
        reinterpret_cast<const float4*>(mat + (size_t)row * M);
    constexpr int M4 = M / 4;   // both 4000 and 20000 divisible by 4

    float best = -CUDART_INF_F;
    int   bvec = (threadIdx.x < M4) ? (int)threadIdx.x : 0;

    int i = threadIdx.x;
    // 4-way unrolled: 4 independent float4 loads + 4 independent max-trees
    for (; i + 3 * 256 < M4; i += 4 * 256) {
        float4 v0 = rp[i];
        float4 v1 = rp[i + 256];
        float4 v2 = rp[i + 512];
        float4 v3 = rp[i + 768];
        float m0 = fmaxf(fmaxf(v0.x, v0.y), fmaxf(v0.z, v0.w));
        float m1 = fmaxf(fmaxf(v1.x, v1.y), fmaxf(v1.z, v1.w));
        float m2 = fmaxf(fmaxf(v2.x, v2.y), fmaxf(v2.z, v2.w));
        float m3 = fmaxf(fmaxf(v3.x, v3.y), fmaxf(v3.z, v3.w));
        // strict '>' keeps the earliest vector on ties (ascending visit order)
        if (m0 > best) { best = m0; bvec = i;       }
        if (m1 > best) { best = m1; bvec = i + 256; }
        if (m2 > best) { best = m2; bvec = i + 512; }
        if (m3 > best) { best = m3; bvec = i + 768; }
    }
    for (; i < M4; i += 256) {
        float4 v = rp[i];
        float m = fmaxf(fmaxf(v.x, v.y), fmaxf(v.z, v.w));
        if (m > best) { best = m; bvec = i; }
    }

    // Recover lane within winning vector (first equality = smallest index).
    // best is bit-identical to one of the 4 elements, so '==' is exact.
    {
        float4 v = rp[bvec];
        int b = bvec * 4;
        int bidx = b + 3;
        if (v.z == best) bidx = b + 2;
        if (v.y == best) bidx = b + 1;
        if (v.x == best) bidx = b;
        bvec = bidx;
    }
    int bidx = bvec;

    // Warp reduce (tie-break: smaller index wins on equal value)
    #pragma unroll
    for (int off = 16; off > 0; off >>= 1) {
        float ov = __shfl_down_sync(0xFFFFFFFFu, best, off);
        int   oi = __shfl_down_sync(0xFFFFFFFFu, bidx, off);
        if (ov > best || (ov == best && oi < bidx)) { best = ov; bidx = oi; }
    }

    // Block reduce across 8 warps
    __shared__ float s_val[8];
    __shared__ int   s_idx[8];
    const int wid = threadIdx.x >> 5;
    const int lid = threadIdx.x & 31;
    if (lid == 0) { s_val[wid] = best; s_idx[wid] = bidx; }
    __syncthreads();
    if (wid == 0) {
        best = (lid < 8) ? s_val[lid] : -CUDART_INF_F;
        bidx = (lid < 8) ? s_idx[lid] : 0x7FFFFFFF;
        #pragma unroll
        for (int off = 4; off > 0; off >>= 1) {
            float ov = __shfl_down_sync(0xFFFFFFFFu, best, off);
            int   oi = __shfl_down_sync(0xFFFFFFFFu, bidx, off);
            if (ov > best || (ov == best && oi < bidx)) { best = ov; bidx = oi; }
        }
        if (lid == 0) out_idx[row] = bidx;
    }
}

// Merged launch: blocks [0, NROWS) do the big Substitute rows (scheduled
// first to minimize the tail), blocks [NROWS, 2*NROWS) do Recommended rows.
__global__ void __launch_bounds__(256) argmax_both_kernel(
    const float* __restrict__ rec, const float* __restrict__ sub,
    int* __restrict__ ri, int* __restrict__ si)
{
    if (blockIdx.x < NROWS)
        row_argmax<M_SUB>(sub, blockIdx.x, si);
    else
        row_argmax<M_REC>(rec, blockIdx.x - NROWS, ri);
}

// ---------------------------------------------------------------------------
// Gathers: p_self, Tprefer (out[0:N]), Thaptic (out[2N:3N])
// NOTE: Vid is int32 on-device (JAX default config downcasts jnp.int64).
// ---------------------------------------------------------------------------
__global__ void gather_kernel(const float* __restrict__ preference,
                              const float* __restrict__ structure,
                              const int* __restrict__ Vid,
                              float* __restrict__ out)
{
    const int i = blockIdx.x * blockDim.x + threadIdx.x;
    if (i >= NROWS) return;
    const int r = g_ri[i];
    const int s = g_si[i];
    const float ps = __ldg(&preference[(size_t)s * NROWS + i]);
    g_pself[i] = ps;
    const int v = Vid[MAXG + r];                 // vid_s[ri[i]], 0 <= v < P
    const float po = __ldg(&preference[(size_t)v * NROWS + i]);
    out[i] = ps - po;                                              // Tprefer
    out[2 * NROWS + i] = __ldg(&structure[(size_t)s * M_REC + r]); // Thaptic
}

// ---------------------------------------------------------------------------
// Tsocial stage 1: 16 i-tiles x 16 j-slices = 256 blocks (fills the chip).
// Each thread owns one i, scans one 256-entry j-slice from shared (packed
// int2 {si, p} -> one LDS.64 per iteration). Deterministic partials.
// ---------------------------------------------------------------------------
__global__ void __launch_bounds__(256) tsocial_partial_kernel()
{
    const int itile = blockIdx.x & (NJSL - 1);
    const int jsl   = blockIdx.x >> 4;

    __shared__ int2 sj[JLEN];
    {
        const int j = jsl * JLEN + threadIdx.x;
        sj[threadIdx.x] = make_int2(g_si[j], __float_as_int(g_pself[j]));
    }
    __syncthreads();

    const int i    = itile * 256 + threadIdx.x;
    const int si_i = g_si[i];
    const float p_i = g_pself[i];
    float acc = 0.0f;
    #pragma unroll 8
    for (int jj = 0; jj < JLEN; jj++) {
        const int2 v = sj[jj];
        if (v.x == si_i) acc += fminf(p_i, __int_as_float(v.y));
    }
    g_part[jsl * NROWS + i] = acc;
}

// Tsocial stage 2: sum the 16 partials, subtract self-term, write out[N:2N].
__global__ void __launch_bounds__(256) tsocial_reduce_kernel(float* __restrict__ out)
{
    const int i = blockIdx.x * 256 + threadIdx.x;
    float acc = 0.0f;
    #pragma unroll
    for (int s = 0; s < NJSL; s++) acc += g_part[s * NROWS + i];
    // The scan included j == i (si_i == si_i always); fminf(p_i,p_i) == p_i.
    out[NROWS + i] = acc - g_pself[i];
}

// ---------------------------------------------------------------------------
extern "C" void kernel_launch(void* const* d_in, const int* in_sizes, int n_in,
                              void* d_out, int out_size)
{
    const float* Recommended_m = (const float*)d_in[0];
    const float* Substitute_m  = (const float*)d_in[1];
    // d_in[2] ItemGroups_m : unused
    const int*   Vid           = (const int*)d_in[3];
    // d_in[4..7] VUU/KUU/Vscore/Kscore : unused
    const float* preference    = (const float*)d_in[8];
    const float* structure     = (const float*)d_in[9];
    float* out = (float*)d_out;

    int* d_ri; int* d_si;
    cudaGetSymbolAddress((void**)&d_ri, g_ri);
    cudaGetSymbolAddress((void**)&d_si, g_si);

    argmax_both_kernel<<<2 * NROWS, 256>>>(Recommended_m, Substitute_m, d_ri, d_si);
    gather_kernel<<<(NROWS + 255) / 256, 256>>>(preference, structure, Vid, out);
    tsocial_partial_kernel<<<NJSL * NJSL, 256>>>();
    tsocial_reduce_kernel<<<NROWS / 256, 256>>>(out);
}